// round 12
// baseline (speedup 1.0000x reference)
#include <cuda_runtime.h>
#include <stdint.h>

#define CIN   320
#define COUT  320
#define KTAPS 9
#define NPIX  65536
#define HWSZ  4096

// scratch (__device__ globals: allocation-free rule)
__device__ __align__(128) int8_t g_xq[(size_t)NPIX * CIN];          // [pix][ci]
__device__ __align__(128) int8_t g_wq[(size_t)KTAPS * COUT * CIN];  // [kpos][co][ci]
__device__ float g_bint8[COUT];

__device__ __forceinline__ float clamp127(float v) {
    return fminf(127.0f, fmaxf(-127.0f, v));
}

// ---------------------------------------------------------------------------
// Kernel 1: quantize x (NCHW fp32 -> NHWC int8) via smem transpose.
// ---------------------------------------------------------------------------
#define QP 80
__global__ __launch_bounds__(256) void quant_x_kernel(const float* __restrict__ x,
                                                      const float* __restrict__ step_x) {
    __shared__ int8_t s[64 * QP];
    const float st = *step_x;
    const int tid = threadIdx.x;
    const int ptile = blockIdx.x;
    const int ctile = blockIdx.y;
    const int n = ptile >> 6;
    const int hw0 = (ptile & 63) << 6;
    const float* xb = x + (((size_t)(n * CIN + ctile * 64)) << 12) + hw0;

#pragma unroll
    for (int k = 0; k < 4; k++) {
        int idx = tid + 256 * k;
        int ci = idx >> 4;
        int p4 = (idx & 15) << 2;
        float4 f = *(const float4*)(xb + (((size_t)ci) << 12) + p4);
        s[(p4 + 0) * QP + ci] = (int8_t)clamp127(rintf(__fdiv_rn(f.x, st)));
        s[(p4 + 1) * QP + ci] = (int8_t)clamp127(rintf(__fdiv_rn(f.y, st)));
        s[(p4 + 2) * QP + ci] = (int8_t)clamp127(rintf(__fdiv_rn(f.z, st)));
        s[(p4 + 3) * QP + ci] = (int8_t)clamp127(rintf(__fdiv_rn(f.w, st)));
    }
    __syncthreads();
    {
        int p = tid >> 2;
        int ch = (tid & 3) * 16;
        int4 v = *(const int4*)(s + p * QP + ch);
        *(int4*)(g_xq + (size_t)((n << 12) + hw0 + p) * CIN + ctile * 64 + ch) = v;
    }
}

// ---------------------------------------------------------------------------
// Kernel 2: quantize w  (OIHW fp32 -> [kpos][co][ci] int8)
// ---------------------------------------------------------------------------
__global__ void quant_w_kernel(const float* __restrict__ w,
                               const float* __restrict__ step_w) {
    float s = *step_w;
    int idx = blockIdx.x * 256 + threadIdx.x;
    if (idx >= KTAPS * COUT * CIN) return;
    int kpos = idx / (COUT * CIN);
    int r = idx % (COUT * CIN);
    int co = r / CIN;
    int ci = r % CIN;
    float v = clamp127(rintf(__fdiv_rn(w[(size_t)(co * CIN + ci) * KTAPS + kpos], s)));
    g_wq[idx] = (int8_t)v;
}

// ---------------------------------------------------------------------------
// Kernel 3: quantized bias
// ---------------------------------------------------------------------------
__global__ void bias_kernel(const float* __restrict__ bias,
                            const float* __restrict__ step_b,
                            const float* __restrict__ step_x,
                            const float* __restrict__ step_w,
                            const float* __restrict__ shift) {
    int co = blockIdx.x * blockDim.x + threadIdx.x;
    if (co >= COUT) return;
    float sb = *step_b;
    float xs = __fdiv_rn(1.0f, *step_x);
    float ws = __fdiv_rn(1.0f, *step_w);
    float sh = *shift;
    float bi = clamp127(rintf(__fdiv_rn(bias[co], sb)));
    float bdeq = __fmul_rn(bi, sb);
    float t = __fmul_rn(__fmul_rn(__fmul_rn(bdeq, sh), xs), ws);
    g_bint8[co] = clamp127(rintf(t));
}

// ---------------------------------------------------------------------------
// Kernel 4: UNIFIED conv — 3-deep cp.async pipeline + LDSM fragments.
//   45 k64-units (9 taps x 5 ck). IMMA stream: units 0..15 (16 stages);
//   dp4a stream: units 16..44 (29 stages). One barrier per stage,
//   wait_group 1 (2 stages of LDGSTS hiding). dp4a accumulates into the
//   IMMA fragment accumulators. 8 warps, 64co x 128pix, 2 CTAs/SM.
// ---------------------------------------------------------------------------
#define NSI 16
#define NSD 29
#define NST 29
#define UD_BASE NSI
#define NBUF 3
#define STRD 80             // smem row stride (bytes), conflict-free
#define SW   20

// dynamic smem layout (bytes)
#define SZ_A (64 * STRD)
#define SZ_B (128 * STRD)
#define OFF_AI 0
#define OFF_BI (OFF_AI + NBUF * SZ_A)        // 15360
#define OFF_AD (OFF_BI + NBUF * SZ_B)        // 46080
#define OFF_BD (OFF_AD + NBUF * SZ_A)        // 61440
#define SMEM_TOTAL (OFF_BD + NBUF * SZ_B)    // 92160

__device__ __forceinline__ uint32_t smem_u32(const void* p) {
    uint32_t a;
    asm("{ .reg .u64 t; cvta.to.shared.u64 t, %1; cvt.u32.u64 %0, t; }" : "=r"(a) : "l"(p));
    return a;
}
__device__ __forceinline__ void cpa16(uint32_t dst, const void* src) {
    asm volatile("cp.async.cg.shared.global [%0], [%1], 16;" :: "r"(dst), "l"(src));
}
__device__ __forceinline__ void cpa16z(uint32_t dst, const void* src, bool ok) {
    int sz = ok ? 16 : 0;
    asm volatile("cp.async.cg.shared.global [%0], [%1], 16, %2;" :: "r"(dst), "l"(src), "r"(sz));
}
__device__ __forceinline__ void ldsm4(uint32_t& r0, uint32_t& r1, uint32_t& r2, uint32_t& r3,
                                      uint32_t addr) {
    asm volatile("ldmatrix.sync.aligned.m8n8.x4.shared.b16 {%0,%1,%2,%3}, [%4];"
                 : "=r"(r0), "=r"(r1), "=r"(r2), "=r"(r3) : "r"(addr));
}
__device__ __forceinline__ void mma_s8(int* c, const uint32_t* a, const uint32_t* b) {
    asm volatile(
        "mma.sync.aligned.m16n8k32.row.col.s32.s8.s8.s32 "
        "{%0,%1,%2,%3}, {%4,%5,%6,%7}, {%8,%9}, {%0,%1,%2,%3};"
        : "+r"(c[0]), "+r"(c[1]), "+r"(c[2]), "+r"(c[3])
        : "r"(a[0]), "r"(a[1]), "r"(a[2]), "r"(a[3]),
          "r"(b[0]), "r"(b[1]));
}

__global__ __launch_bounds__(256, 2)
void conv_unified_kernel(float* __restrict__ out, const float* __restrict__ shift_ptr) {
    extern __shared__ __align__(16) int8_t smem[];
    const uint32_t sb = smem_u32(smem);
    const uint32_t sbAi = sb + OFF_AI;
    const uint32_t sbBi = sb + OFF_BI;
    const uint32_t sbAd = sb + OFF_AD;
    const uint32_t sbBd = sb + OFF_BD;

    const int tid = threadIdx.x;
    const int wid = tid >> 5, lane = tid & 31;
    const int warp_m = wid >> 2, warp_n = wid & 3;
    const int qq = lane & 3, rr = lane >> 2;
    const int pix_base = blockIdx.x * 128;
    const int co_base = blockIdx.y * 64;
    const int n = pix_base >> 12;
    const int H0 = (pix_base & 4095) >> 6;

    int acc[2][4][4];
#pragma unroll
    for (int i = 0; i < 2; i++)
#pragma unroll
        for (int j = 0; j < 4; j++)
#pragma unroll
            for (int k = 0; k < 4; k++) acc[i][j][k] = 0;

    // cp.async loader geometry
    const int rowA = tid >> 2;
    const int qA   = tid & 3;

    // issue stage data for unit u into buffer buf of a stream
    auto issueU = [&](int u, int buf, uint32_t sA, uint32_t sB) {
        int kpos = u / 5, ck = u % 5;
        int dh = kpos / 3 - 1, dw = kpos % 3 - 1;
        cpa16(sA + buf * SZ_A + rowA * STRD + qA * 16,
              g_wq + ((size_t)kpos * COUT + co_base + rowA) * CIN + ck * 64 + qA * 16);
#pragma unroll
        for (int e = 0; e < 2; e++) {
            int idx = tid + e * 256;
            int row = idx >> 2, q = idx & 3;
            int hs = H0 + (row >> 6) + dh;
            int ws = (row & 63) + dw;
            bool ok = (hs >= 0) && (hs < 64) && (ws >= 0) && (ws < 64);
            const int8_t* src = g_xq +
                (ok ? (size_t)((n << 12) + (hs << 6) + ws) * CIN + ck * 64 + q * 16 : 0);
            cpa16z(sB + buf * SZ_B + row * STRD + q * 16, src, ok);
        }
    };

    // LDSM per-lane offsets
    const uint32_t aLane = (uint32_t)((lane & 15) * STRD + (lane >> 4) * 16);
    const uint32_t bLane = (uint32_t)(((lane >> 4) * 8 + (lane & 7)) * STRD + ((lane >> 3) & 1) * 16);

    // dp4a fragment-matched bases
    const int rA0 = warp_m * 32 + rr;
    const int cB0 = warp_n * 32 + qq * 2;
    int8_t* smem8 = smem;

    // prologue: issue stages 0 and 1 (both streams), separate commit groups
    issueU(0, 0, sbAi, sbBi);
    issueU(UD_BASE + 0, 0, sbAd, sbBd);
    asm volatile("cp.async.commit_group;" ::: "memory");
    issueU(1, 1, sbAi, sbBi);
    issueU(UD_BASE + 1, 1, sbAd, sbBd);
    asm volatile("cp.async.commit_group;" ::: "memory");

    int buf = 0;        // buffer of stage i
#pragma unroll 1
    for (int i = 0; i < NST; i++) {
        asm volatile("cp.async.wait_group 1;" ::: "memory");   // stage i data (mine) done
        __syncthreads();                                       // all threads' data visible;
                                                               // stage i-1 readers retired
        // issue stage i+2 into buffer (i+2)%3 (last read at stage i-1)
        {
            int nb = buf + 2; if (nb >= NBUF) nb -= NBUF;
            if (i + 2 < NSI) issueU(i + 2, nb, sbAi, sbBi);
            if (i + 2 < NSD) issueU(UD_BASE + i + 2, nb, sbAd, sbBd);
            asm volatile("cp.async.commit_group;" ::: "memory");
        }

        // ---- IMMA compute on buf (if stream active): 2 k32 sub-blocks ----
        if (i < NSI) {
            const uint32_t aBase = sbAi + buf * SZ_A;
            const uint32_t bBase = sbBi + buf * SZ_B;
#pragma unroll
            for (int kk = 0; kk < 2; kk++) {
                uint32_t a[2][4], b[4][2];
#pragma unroll
                for (int mt = 0; mt < 2; mt++) {
                    uint32_t addr = aBase + (uint32_t)((warp_m * 32 + mt * 16) * STRD + kk * 32) + aLane;
                    ldsm4(a[mt][0], a[mt][1], a[mt][2], a[mt][3], addr);
                }
#pragma unroll
                for (int p = 0; p < 2; p++) {
                    uint32_t addr = bBase + (uint32_t)((warp_n * 32 + p * 16) * STRD + kk * 32) + bLane;
                    ldsm4(b[2 * p][0], b[2 * p][1], b[2 * p + 1][0], b[2 * p + 1][1], addr);
                }
#pragma unroll
                for (int mt = 0; mt < 2; mt++)
#pragma unroll
                    for (int nt = 0; nt < 4; nt++)
                        mma_s8(acc[mt][nt], a[mt], b[nt]);
            }
        }

        // ---- dp4a compute: stage i, all 4 quarters, same accumulators ----
        {
            const int8_t* aT = smem8 + OFF_AD + buf * SZ_A;
            const int8_t* bT = smem8 + OFF_BD + buf * SZ_B;
#pragma unroll
            for (int s16 = 0; s16 < 4; s16++) {
                int4 ar[4];
#pragma unroll
                for (int mh = 0; mh < 4; mh++) {
                    int row = rA0 + (mh >> 1) * 16 + (mh & 1) * 8;
                    ar[mh] = *(const int4*)(aT + row * STRD + s16 * 16);
                }
#pragma unroll
                for (int nt = 0; nt < 4; nt++) {
                    int col = cB0 + nt * 8;
                    int4 b0 = *(const int4*)(bT + col * STRD + s16 * 16);
                    int4 b1 = *(const int4*)(bT + (col + 1) * STRD + s16 * 16);
#pragma unroll
                    for (int mh = 0; mh < 4; mh++) {
                        const int mt = mh >> 1, hh = mh & 1;
                        int v0 = acc[mt][nt][hh * 2 + 0];
                        int v1 = acc[mt][nt][hh * 2 + 1];
                        v0 = __dp4a(ar[mh].x, b0.x, v0);
                        v1 = __dp4a(ar[mh].x, b1.x, v1);
                        v0 = __dp4a(ar[mh].y, b0.y, v0);
                        v1 = __dp4a(ar[mh].y, b1.y, v1);
                        v0 = __dp4a(ar[mh].z, b0.z, v0);
                        v1 = __dp4a(ar[mh].z, b1.z, v1);
                        v0 = __dp4a(ar[mh].w, b0.w, v0);
                        v1 = __dp4a(ar[mh].w, b1.w, v1);
                        acc[mt][nt][hh * 2 + 0] = v0;
                        acc[mt][nt][hh * 2 + 1] = v1;
                    }
                }
            }
        }

        if (++buf >= NBUF) buf -= NBUF;
    }

    // =================== epilogue (acc holds all 9 taps) ===================
    {
        const float shift = *shift_ptr;
        const int ohw_base = pix_base & 4095;
#pragma unroll
        for (int mt = 0; mt < 2; mt++) {
#pragma unroll
            for (int hh = 0; hh < 2; hh++) {
                int co = co_base + warp_m * 32 + mt * 16 + rr + hh * 8;
                float bb = g_bint8[co];
#pragma unroll
                for (int nt = 0; nt < 4; nt++) {
                    int pix_l = warp_n * 32 + nt * 8 + qq * 2;
                    int a0 = acc[mt][nt][hh * 2 + 0];
                    int a1 = acc[mt][nt][hh * 2 + 1];
                    float v0 = clamp127(rintf(__int2float_rn(a0) * shift));
                    float v1 = clamp127(rintf(__int2float_rn(a1) * shift));
                    v0 = clamp127(v0 + bb);
                    v1 = clamp127(v1 + bb);
                    float* op = out + (((size_t)(n * COUT + co)) << 12) + ohw_base + pix_l;
                    *(float2*)op = make_float2(v0, v1);
                }
            }
        }
    }
}

// ---------------------------------------------------------------------------
extern "C" void kernel_launch(void* const* d_in, const int* in_sizes, int n_in,
                              void* d_out, int out_size) {
    const float* x = (const float*)d_in[0];
    const float* wt = (const float*)d_in[1];
    const float* bias = (const float*)d_in[2];
    const float* step_x = (const float*)d_in[3];
    const float* step_w = (const float*)d_in[4];
    const float* step_b = (const float*)d_in[5];
    const float* shift = (const float*)d_in[6];
    float* out = (float*)d_out;

    cudaFuncSetAttribute(conv_unified_kernel,
                         cudaFuncAttributeMaxDynamicSharedMemorySize, SMEM_TOTAL);

    quant_x_kernel<<<dim3(1024, 5), 256>>>(x, step_x);

    int wtotal = KTAPS * COUT * CIN;
    quant_w_kernel<<<(wtotal + 255) / 256, 256>>>(wt, step_w);

    bias_kernel<<<2, 160>>>(bias, step_b, step_x, step_w, shift);

    conv_unified_kernel<<<dim3(NPIX / 128, COUT / 64), 256, SMEM_TOTAL>>>(out, shift);
}

// round 13
// speedup vs baseline: 1.0925x; 1.0925x over previous
#include <cuda_runtime.h>
#include <stdint.h>

#define CIN   320
#define COUT  320
#define KTAPS 9
#define NPIX  65536
#define HWSZ  4096

// scratch (__device__ globals: allocation-free rule)
__device__ __align__(128) int8_t g_xq[(size_t)NPIX * CIN];          // [pix][ci]
__device__ __align__(128) int8_t g_wq[(size_t)KTAPS * COUT * CIN];  // [kpos][co][ci]
__device__ float g_bint8[COUT];

__device__ __forceinline__ float clamp127(float v) {
    return fminf(127.0f, fmaxf(-127.0f, v));
}

// ---------------------------------------------------------------------------
// Kernel 1: quantize x (NCHW fp32 -> NHWC int8) via smem transpose.
// ---------------------------------------------------------------------------
#define QP 80
__global__ __launch_bounds__(256) void quant_x_kernel(const float* __restrict__ x,
                                                      const float* __restrict__ step_x) {
    __shared__ int8_t s[64 * QP];
    const float st = *step_x;
    const int tid = threadIdx.x;
    const int ptile = blockIdx.x;
    const int ctile = blockIdx.y;
    const int n = ptile >> 6;
    const int hw0 = (ptile & 63) << 6;
    const float* xb = x + (((size_t)(n * CIN + ctile * 64)) << 12) + hw0;

#pragma unroll
    for (int k = 0; k < 4; k++) {
        int idx = tid + 256 * k;
        int ci = idx >> 4;
        int p4 = (idx & 15) << 2;
        float4 f = *(const float4*)(xb + (((size_t)ci) << 12) + p4);
        s[(p4 + 0) * QP + ci] = (int8_t)clamp127(rintf(__fdiv_rn(f.x, st)));
        s[(p4 + 1) * QP + ci] = (int8_t)clamp127(rintf(__fdiv_rn(f.y, st)));
        s[(p4 + 2) * QP + ci] = (int8_t)clamp127(rintf(__fdiv_rn(f.z, st)));
        s[(p4 + 3) * QP + ci] = (int8_t)clamp127(rintf(__fdiv_rn(f.w, st)));
    }
    __syncthreads();
    {
        int p = tid >> 2;
        int ch = (tid & 3) * 16;
        int4 v = *(const int4*)(s + p * QP + ch);
        *(int4*)(g_xq + (size_t)((n << 12) + hw0 + p) * CIN + ctile * 64 + ch) = v;
    }
}

// ---------------------------------------------------------------------------
// Kernel 2: quantize w  (OIHW fp32 -> [kpos][co][ci] int8)
// ---------------------------------------------------------------------------
__global__ void quant_w_kernel(const float* __restrict__ w,
                               const float* __restrict__ step_w) {
    float s = *step_w;
    int idx = blockIdx.x * 256 + threadIdx.x;
    if (idx >= KTAPS * COUT * CIN) return;
    int kpos = idx / (COUT * CIN);
    int r = idx % (COUT * CIN);
    int co = r / CIN;
    int ci = r % CIN;
    float v = clamp127(rintf(__fdiv_rn(w[(size_t)(co * CIN + ci) * KTAPS + kpos], s)));
    g_wq[idx] = (int8_t)v;
}

// ---------------------------------------------------------------------------
// Kernel 3: quantized bias
// ---------------------------------------------------------------------------
__global__ void bias_kernel(const float* __restrict__ bias,
                            const float* __restrict__ step_b,
                            const float* __restrict__ step_x,
                            const float* __restrict__ step_w,
                            const float* __restrict__ shift) {
    int co = blockIdx.x * blockDim.x + threadIdx.x;
    if (co >= COUT) return;
    float sb = *step_b;
    float xs = __fdiv_rn(1.0f, *step_x);
    float ws = __fdiv_rn(1.0f, *step_w);
    float sh = *shift;
    float bi = clamp127(rintf(__fdiv_rn(bias[co], sb)));
    float bdeq = __fmul_rn(bi, sb);
    float t = __fmul_rn(__fmul_rn(__fmul_rn(bdeq, sh), xs), ws);
    g_bint8[co] = clamp127(rintf(t));
}

// ---------------------------------------------------------------------------
// Kernel 4: UNIFIED conv — 3-deep cp.async pipeline + LDSM fragments.
//   45 k64-units (9 taps x 5 ck). Split tuned by the ISSUE-cost model:
//   IMMA stream: units 0..26 (27 stages); dp4a stream: units 27..44 (18
//   stages, ends early — tail stages are pure IMMA). dp4a accumulates into
//   the IMMA fragment accumulators. 8 warps, 64co x 128pix, 2 CTAs/SM.
// ---------------------------------------------------------------------------
#define NSI 27
#define NSD 18
#define NST 27
#define UD_BASE NSI
#define NBUF 3
#define STRD 80             // smem row stride (bytes), conflict-free
#define SW   20

// dynamic smem layout (bytes)
#define SZ_A (64 * STRD)
#define SZ_B (128 * STRD)
#define OFF_AI 0
#define OFF_BI (OFF_AI + NBUF * SZ_A)        // 15360
#define OFF_AD (OFF_BI + NBUF * SZ_B)        // 46080
#define OFF_BD (OFF_AD + NBUF * SZ_A)        // 61440
#define SMEM_TOTAL (OFF_BD + NBUF * SZ_B)    // 92160

__device__ __forceinline__ uint32_t smem_u32(const void* p) {
    uint32_t a;
    asm("{ .reg .u64 t; cvta.to.shared.u64 t, %1; cvt.u32.u64 %0, t; }" : "=r"(a) : "l"(p));
    return a;
}
__device__ __forceinline__ void cpa16(uint32_t dst, const void* src) {
    asm volatile("cp.async.cg.shared.global [%0], [%1], 16;" :: "r"(dst), "l"(src));
}
__device__ __forceinline__ void cpa16z(uint32_t dst, const void* src, bool ok) {
    int sz = ok ? 16 : 0;
    asm volatile("cp.async.cg.shared.global [%0], [%1], 16, %2;" :: "r"(dst), "l"(src), "r"(sz));
}
__device__ __forceinline__ void ldsm4(uint32_t& r0, uint32_t& r1, uint32_t& r2, uint32_t& r3,
                                      uint32_t addr) {
    asm volatile("ldmatrix.sync.aligned.m8n8.x4.shared.b16 {%0,%1,%2,%3}, [%4];"
                 : "=r"(r0), "=r"(r1), "=r"(r2), "=r"(r3) : "r"(addr));
}
__device__ __forceinline__ void mma_s8(int* c, const uint32_t* a, const uint32_t* b) {
    asm volatile(
        "mma.sync.aligned.m16n8k32.row.col.s32.s8.s8.s32 "
        "{%0,%1,%2,%3}, {%4,%5,%6,%7}, {%8,%9}, {%0,%1,%2,%3};"
        : "+r"(c[0]), "+r"(c[1]), "+r"(c[2]), "+r"(c[3])
        : "r"(a[0]), "r"(a[1]), "r"(a[2]), "r"(a[3]),
          "r"(b[0]), "r"(b[1]));
}

__global__ __launch_bounds__(256, 2)
void conv_unified_kernel(float* __restrict__ out, const float* __restrict__ shift_ptr) {
    extern __shared__ __align__(16) int8_t smem[];
    const uint32_t sb = smem_u32(smem);
    const uint32_t sbAi = sb + OFF_AI;
    const uint32_t sbBi = sb + OFF_BI;
    const uint32_t sbAd = sb + OFF_AD;
    const uint32_t sbBd = sb + OFF_BD;

    const int tid = threadIdx.x;
    const int wid = tid >> 5, lane = tid & 31;
    const int warp_m = wid >> 2, warp_n = wid & 3;
    const int qq = lane & 3, rr = lane >> 2;
    const int pix_base = blockIdx.x * 128;
    const int co_base = blockIdx.y * 64;
    const int n = pix_base >> 12;
    const int H0 = (pix_base & 4095) >> 6;

    int acc[2][4][4];
#pragma unroll
    for (int i = 0; i < 2; i++)
#pragma unroll
        for (int j = 0; j < 4; j++)
#pragma unroll
            for (int k = 0; k < 4; k++) acc[i][j][k] = 0;

    // cp.async loader geometry
    const int rowA = tid >> 2;
    const int qA   = tid & 3;

    // issue stage data for unit u into buffer buf of a stream
    auto issueU = [&](int u, int buf, uint32_t sA, uint32_t sB) {
        int kpos = u / 5, ck = u % 5;
        int dh = kpos / 3 - 1, dw = kpos % 3 - 1;
        cpa16(sA + buf * SZ_A + rowA * STRD + qA * 16,
              g_wq + ((size_t)kpos * COUT + co_base + rowA) * CIN + ck * 64 + qA * 16);
#pragma unroll
        for (int e = 0; e < 2; e++) {
            int idx = tid + e * 256;
            int row = idx >> 2, q = idx & 3;
            int hs = H0 + (row >> 6) + dh;
            int ws = (row & 63) + dw;
            bool ok = (hs >= 0) && (hs < 64) && (ws >= 0) && (ws < 64);
            const int8_t* src = g_xq +
                (ok ? (size_t)((n << 12) + (hs << 6) + ws) * CIN + ck * 64 + q * 16 : 0);
            cpa16z(sB + buf * SZ_B + row * STRD + q * 16, src, ok);
        }
    };

    // LDSM per-lane offsets
    const uint32_t aLane = (uint32_t)((lane & 15) * STRD + (lane >> 4) * 16);
    const uint32_t bLane = (uint32_t)(((lane >> 4) * 8 + (lane & 7)) * STRD + ((lane >> 3) & 1) * 16);

    // dp4a fragment-matched bases
    const int rA0 = warp_m * 32 + rr;
    const int cB0 = warp_n * 32 + qq * 2;
    int8_t* smem8 = smem;

    // prologue: issue stages 0 and 1 (both streams), separate commit groups
    issueU(0, 0, sbAi, sbBi);
    issueU(UD_BASE + 0, 0, sbAd, sbBd);
    asm volatile("cp.async.commit_group;" ::: "memory");
    issueU(1, 1, sbAi, sbBi);
    issueU(UD_BASE + 1, 1, sbAd, sbBd);
    asm volatile("cp.async.commit_group;" ::: "memory");

    int buf = 0;        // buffer of stage i
#pragma unroll 1
    for (int i = 0; i < NST; i++) {
        asm volatile("cp.async.wait_group 1;" ::: "memory");   // stage i data (mine) done
        __syncthreads();                                       // all threads' data visible;
                                                               // stage i-1 readers retired
        // issue stage i+2 into buffer (i+2)%3 (last read at stage i-1)
        {
            int nb = buf + 2; if (nb >= NBUF) nb -= NBUF;
            if (i + 2 < NSI) issueU(i + 2, nb, sbAi, sbBi);
            if (i + 2 < NSD) issueU(UD_BASE + i + 2, nb, sbAd, sbBd);
            asm volatile("cp.async.commit_group;" ::: "memory");
        }

        // ---- IMMA compute on buf: 2 k32 sub-blocks ----
        if (i < NSI) {
            const uint32_t aBase = sbAi + buf * SZ_A;
            const uint32_t bBase = sbBi + buf * SZ_B;
#pragma unroll
            for (int kk = 0; kk < 2; kk++) {
                uint32_t a[2][4], b[4][2];
#pragma unroll
                for (int mt = 0; mt < 2; mt++) {
                    uint32_t addr = aBase + (uint32_t)((warp_m * 32 + mt * 16) * STRD + kk * 32) + aLane;
                    ldsm4(a[mt][0], a[mt][1], a[mt][2], a[mt][3], addr);
                }
#pragma unroll
                for (int p = 0; p < 2; p++) {
                    uint32_t addr = bBase + (uint32_t)((warp_n * 32 + p * 16) * STRD + kk * 32) + bLane;
                    ldsm4(b[2 * p][0], b[2 * p][1], b[2 * p + 1][0], b[2 * p + 1][1], addr);
                }
#pragma unroll
                for (int mt = 0; mt < 2; mt++)
#pragma unroll
                    for (int nt = 0; nt < 4; nt++)
                        mma_s8(acc[mt][nt], a[mt], b[nt]);
            }
        }

        // ---- dp4a compute: stage i (while stream active), 4 quarters ----
        if (i < NSD) {
            const int8_t* aT = smem8 + OFF_AD + buf * SZ_A;
            const int8_t* bT = smem8 + OFF_BD + buf * SZ_B;
#pragma unroll
            for (int s16 = 0; s16 < 4; s16++) {
                int4 ar[4];
#pragma unroll
                for (int mh = 0; mh < 4; mh++) {
                    int row = rA0 + (mh >> 1) * 16 + (mh & 1) * 8;
                    ar[mh] = *(const int4*)(aT + row * STRD + s16 * 16);
                }
#pragma unroll
                for (int nt = 0; nt < 4; nt++) {
                    int col = cB0 + nt * 8;
                    int4 b0 = *(const int4*)(bT + col * STRD + s16 * 16);
                    int4 b1 = *(const int4*)(bT + (col + 1) * STRD + s16 * 16);
#pragma unroll
                    for (int mh = 0; mh < 4; mh++) {
                        const int mt = mh >> 1, hh = mh & 1;
                        int v0 = acc[mt][nt][hh * 2 + 0];
                        int v1 = acc[mt][nt][hh * 2 + 1];
                        v0 = __dp4a(ar[mh].x, b0.x, v0);
                        v1 = __dp4a(ar[mh].x, b1.x, v1);
                        v0 = __dp4a(ar[mh].y, b0.y, v0);
                        v1 = __dp4a(ar[mh].y, b1.y, v1);
                        v0 = __dp4a(ar[mh].z, b0.z, v0);
                        v1 = __dp4a(ar[mh].z, b1.z, v1);
                        v0 = __dp4a(ar[mh].w, b0.w, v0);
                        v1 = __dp4a(ar[mh].w, b1.w, v1);
                        acc[mt][nt][hh * 2 + 0] = v0;
                        acc[mt][nt][hh * 2 + 1] = v1;
                    }
                }
            }
        }

        if (++buf >= NBUF) buf -= NBUF;
    }

    // =================== epilogue (acc holds all 9 taps) ===================
    {
        const float shift = *shift_ptr;
        const int ohw_base = pix_base & 4095;
#pragma unroll
        for (int mt = 0; mt < 2; mt++) {
#pragma unroll
            for (int hh = 0; hh < 2; hh++) {
                int co = co_base + warp_m * 32 + mt * 16 + rr + hh * 8;
                float bb = g_bint8[co];
#pragma unroll
                for (int nt = 0; nt < 4; nt++) {
                    int pix_l = warp_n * 32 + nt * 8 + qq * 2;
                    int a0 = acc[mt][nt][hh * 2 + 0];
                    int a1 = acc[mt][nt][hh * 2 + 1];
                    float v0 = clamp127(rintf(__int2float_rn(a0) * shift));
                    float v1 = clamp127(rintf(__int2float_rn(a1) * shift));
                    v0 = clamp127(v0 + bb);
                    v1 = clamp127(v1 + bb);
                    float* op = out + (((size_t)(n * COUT + co)) << 12) + ohw_base + pix_l;
                    *(float2*)op = make_float2(v0, v1);
                }
            }
        }
    }
}

// ---------------------------------------------------------------------------
extern "C" void kernel_launch(void* const* d_in, const int* in_sizes, int n_in,
                              void* d_out, int out_size) {
    const float* x = (const float*)d_in[0];
    const float* wt = (const float*)d_in[1];
    const float* bias = (const float*)d_in[2];
    const float* step_x = (const float*)d_in[3];
    const float* step_w = (const float*)d_in[4];
    const float* step_b = (const float*)d_in[5];
    const float* shift = (const float*)d_in[6];
    float* out = (float*)d_out;

    cudaFuncSetAttribute(conv_unified_kernel,
                         cudaFuncAttributeMaxDynamicSharedMemorySize, SMEM_TOTAL);

    quant_x_kernel<<<dim3(1024, 5), 256>>>(x, step_x);

    int wtotal = KTAPS * COUT * CIN;
    quant_w_kernel<<<(wtotal + 255) / 256, 256>>>(wt, step_w);

    bias_kernel<<<2, 160>>>(bias, step_b, step_x, step_w, shift);

    conv_unified_kernel<<<dim3(NPIX / 128, COUT / 64), 256, SMEM_TOTAL>>>(out, shift);
}